// round 6
// baseline (speedup 1.0000x reference)
#include <cuda_runtime.h>
#include <math.h>

#define NN 100000
#define EE 1600000
#define DD 64
#define EDIM 16
#define SHC 9
#define FEAT 25     // SHC + EDIM
#define TILE_E 256
#define NTILE (EE / TILE_E)   // 6250

typedef unsigned long long u64;

// ---------------- scratch (device globals; no runtime allocation) ----------
__device__ float  g_xt[(size_t)NN * DD];   // node MLP output
__device__ float  g_s [(size_t)NN * DD];   // segment sum -> agg (in place)
__device__ float  g_cnt[NN];               // per-node edge count
__device__ float  g_h [(size_t)NN * DD];   // out MLP result (pre-BN)
__device__ double g_sum[DD];               // BN stats
__device__ double g_sumsq[DD];

__device__ __forceinline__ float silu_f(float a) {
    return a / (1.0f + __expf(-a));
}

// ---------------- packed f32x2 helpers --------------------------------------
__device__ __forceinline__ u64 pk2(float x, float y) {
    u64 r; asm("mov.b64 %0, {%1,%2};" : "=l"(r) : "f"(x), "f"(y)); return r;
}
__device__ __forceinline__ void upk2(u64 v, float& x, float& y) {
    asm("mov.b64 {%0,%1}, %2;" : "=f"(x), "=f"(y) : "l"(v));
}
__device__ __forceinline__ void fma2(u64& d, u64 a, u64 b) {
    asm("fma.rn.f32x2 %0, %1, %2, %0;" : "+l"(d) : "l"(a), "l"(b));
}
__device__ __forceinline__ u64 silu2(u64 p) {
    float a, b; upk2(p, a, b);
    return pk2(silu_f(a), silu_f(b));
}
__device__ __forceinline__ void red_add_v4(float* p, float a, float b, float c, float d) {
    asm volatile("red.global.add.v4.f32 [%0], {%1,%2,%3,%4};"
                 :: "l"(p), "f"(a), "f"(b), "f"(c), "f"(d) : "memory");
}

// ---------------- zero scratch --------------------------------------------
__global__ void zero_kernel() {
    int idx = blockIdx.x * blockDim.x + threadIdx.x;
    int stride = gridDim.x * blockDim.x;
    float4 z = make_float4(0.f, 0.f, 0.f, 0.f);
    for (int i = idx; i < NN * (DD / 4); i += stride)
        ((float4*)g_s)[i] = z;
    for (int i = idx; i < NN; i += stride)
        g_cnt[i] = 0.f;
    if (idx < DD) { g_sum[idx] = 0.0; g_sumsq[idx] = 0.0; }
}

// ---------------- node / output MLP (unchanged) -----------------------------
template <bool IS_OUT>
__global__ __launch_bounds__(128)
void mlp_kernel(const float* __restrict__ x,
                const float* __restrict__ W1, const float* __restrict__ b1,
                const float* __restrict__ W2, const float* __restrict__ b2)
{
    constexpr int IND = IS_OUT ? 128 : 64;
    __shared__ __align__(16) float sW1[IND * DD];
    __shared__ __align__(16) float sW2[DD * DD];
    const int t = threadIdx.x;
    for (int i = t; i < IND * DD; i += 128) sW1[i] = W1[i];
    for (int i = t; i < DD * DD;  i += 128) sW2[i] = W2[i];
    __syncthreads();

    const int id = blockIdx.x * 128 + t;
    const bool valid = (id < NN);
    const int rid = valid ? id : (NN - 1);

    const float4* rowA;
    const float4* rowB = nullptr;
    if (IS_OUT) {
        rowA = (const float4*)(g_s + (size_t)rid * DD);
        rowB = (const float4*)(x   + (size_t)rid * DD);
    } else {
        rowA = (const float4*)(x + (size_t)rid * DD);
    }

    u64 outp[32];
    {
        const ulonglong2* b2v = (const ulonglong2*)b2;
        #pragma unroll
        for (int q = 0; q < 16; q++) { ulonglong2 bv = b2v[q]; outp[2*q] = bv.x; outp[2*q+1] = bv.y; }
    }

    #pragma unroll 1
    for (int ch = 0; ch < 4; ch++) {
        const int base = ch * 16;
        u64 hp[8];
        {
            const ulonglong2* b1v = (const ulonglong2*)(b1 + base);
            #pragma unroll
            for (int q = 0; q < 4; q++) { ulonglong2 bv = b1v[q]; hp[2*q] = bv.x; hp[2*q+1] = bv.y; }
        }
        #pragma unroll 2
        for (int g = 0; g < IND / 4; g++) {
            float4 v;
            if (IS_OUT) v = (g < 16) ? rowA[g] : rowB[g - 16];
            else        v = rowA[g];
            const float fv[4] = {v.x, v.y, v.z, v.w};
            #pragma unroll
            for (int u = 0; u < 4; u++) {
                const u64 fmp = pk2(fv[u], fv[u]);
                const ulonglong2* wr = (const ulonglong2*)(sW1 + (g*4 + u) * DD + base);
                #pragma unroll
                for (int q = 0; q < 4; q++) {
                    ulonglong2 w = wr[q];
                    fma2(hp[2*q], fmp, w.x);
                    fma2(hp[2*q+1], fmp, w.y);
                }
            }
        }
        float h16[16];
        #pragma unroll
        for (int i = 0; i < 8; i++) {
            float a, b; upk2(hp[i], a, b);
            h16[2*i] = silu_f(a); h16[2*i+1] = silu_f(b);
        }
        #pragma unroll
        for (int kk = 0; kk < 16; kk++) {
            const u64 hvp = pk2(h16[kk], h16[kk]);
            const ulonglong2* wr = (const ulonglong2*)(sW2 + (base + kk) * DD);
            #pragma unroll
            for (int q = 0; q < 16; q++) {
                ulonglong2 w = wr[q];
                fma2(outp[2*q], hvp, w.x);
                fma2(outp[2*q+1], hvp, w.y);
            }
        }
    }

    float* dst = IS_OUT ? g_h : g_xt;
    if (valid) {
        ulonglong2* o = (ulonglong2*)(dst + (size_t)id * DD);
        #pragma unroll
        for (int q = 0; q < 16; q++) {
            ulonglong2 w; w.x = outp[2*q]; w.y = outp[2*q+1];
            o[q] = w;
        }
    }

    if (IS_OUT) {
        #pragma unroll
        for (int jp = 0; jp < 32; jp++) {
            float va, vb; upk2(outp[jp], va, vb);
            if (!valid) { va = 0.f; vb = 0.f; }
            float s0 = va, q0 = va * va, s1 = vb, q1 = vb * vb;
            #pragma unroll
            for (int o = 16; o; o >>= 1) {
                s0 += __shfl_down_sync(0xffffffffu, s0, o);
                q0 += __shfl_down_sync(0xffffffffu, q0, o);
                s1 += __shfl_down_sync(0xffffffffu, s1, o);
                q1 += __shfl_down_sync(0xffffffffu, q1, o);
            }
            if ((t & 31) == 0) {
                atomicAdd(&g_sum[2*jp],     (double)s0);
                atomicAdd(&g_sumsq[2*jp],   (double)q0);
                atomicAdd(&g_sum[2*jp+1],   (double)s1);
                atomicAdd(&g_sumsq[2*jp+1], (double)q1);
            }
        }
    }
}

// ---------------- fused edge kernel ----------------------------------------
// 256-edge tile; thread (er,nc) computes 8 edges x 8 outputs.
// Weights stored DUPLICATED (each w twice, adjacent) so LDS.128 yields f32x2
// operand pairs directly — no pk2 broadcasts in the inner loops.
// smem layout (floats): sW1d[25*128] | sW2d[64*128] | sRow[256] | sCol[256] | buf[64*256]
__global__ __launch_bounds__(256, 2)
void edge_kernel(const float* __restrict__ pos,
                 const float* __restrict__ edge_attr,
                 const int*   __restrict__ row,
                 const int*   __restrict__ col,
                 const float* __restrict__ W1, const float* __restrict__ b1,
                 const float* __restrict__ W2, const float* __restrict__ b2)
{
    extern __shared__ float smem[];
    float* sW1d = smem;                        // 3200 floats
    float* sW2d = smem + 3200;                 // 8192 floats
    int*   sRow = (int*)(smem + 11392);        // 256 ints
    int*   sCol = (int*)(smem + 11648);        // 256 ints
    float* buf  = smem + 11904;                // 64*256 = 16384 floats

    const int t  = threadIdx.x;
    const int er = t >> 3;     // 0..31
    const int nc = t & 7;      // 0..7

    for (int i = t; i < FEAT * DD; i += 256) {
        float v = W1[i]; int k = i >> 6, j = i & 63;
        sW1d[k*128 + 2*j] = v; sW1d[k*128 + 2*j + 1] = v;
    }
    for (int i = t; i < DD * DD; i += 256) {
        float v = W2[i]; int k = i >> 6, j = i & 63;
        sW2d[k*128 + 2*j] = v; sW2d[k*128 + 2*j + 1] = v;
    }
    u64 bp1[8], bp2[8];
    #pragma unroll
    for (int i = 0; i < 8; i++) {
        float v1 = b1[nc*8 + i], v2 = b2[nc*8 + i];
        bp1[i] = pk2(v1, v1); bp2[i] = pk2(v2, v2);
    }
    __syncthreads();

    // prefetch state for the upcoming tile (random pos gather hidden under scatter)
    int   pr_r, pr_c;
    float pr_dx, pr_dy, pr_dz;
    {
        const int e0 = blockIdx.x * TILE_E + t;
        pr_r = row[e0]; pr_c = col[e0];
        float px = pos[3*pr_r]   - pos[3*pr_c];
        float py = pos[3*pr_r+1] - pos[3*pr_c+1];
        float pz = pos[3*pr_r+2] - pos[3*pr_c+2];
        float len = sqrtf(px*px + py*py + pz*pz + 1e-12f);
        float dx = px / len, dy = py / len, dz = pz / len;
        float n2 = sqrtf(dx*dx + dy*dy + dz*dz) + 1e-10f;
        pr_dx = dx / n2; pr_dy = dy / n2; pr_dz = dz / n2;
    }

    for (int tile = blockIdx.x; tile < NTILE; tile += gridDim.x) {
        const int e = tile * TILE_E + t;

        // ---- phase 1: features -> buf[k][t]; cache row/col ----
        {
            sRow[t] = pr_r; sCol[t] = pr_c;
            const float dx = pr_dx, dy = pr_dy, dz = pr_dz;
            float feat[FEAT];
            feat[0] = 0.28209479177387814f;
            feat[1] = 0.4886025119029199f * dy;
            feat[2] = 0.4886025119029199f * dz;
            feat[3] = 0.4886025119029199f * dx;
            feat[4] = 1.0925484305920792f * dx * dy;
            feat[5] = 1.0925484305920792f * dy * dz;
            feat[6] = 0.31539156525252005f * (3.0f * dz * dz - 1.0f);
            feat[7] = 1.0925484305920792f * dx * dz;
            feat[8] = 0.5462742152960396f * (dx*dx - dy*dy);
            const float4* ea = (const float4*)(edge_attr + (size_t)e * EDIM);
            #pragma unroll
            for (int i = 0; i < 4; i++) {
                float4 v = ea[i];
                feat[SHC + 4*i]   = v.x; feat[SHC + 4*i+1] = v.y;
                feat[SHC + 4*i+2] = v.z; feat[SHC + 4*i+3] = v.w;
            }
            #pragma unroll
            for (int k = 0; k < FEAT; k++) buf[k*TILE_E + t] = feat[k];
            atomicAdd(&g_cnt[pr_c], 1.0f);
        }
        __syncthreads();

        // ---- phase 2: GEMM1  H = A1[256x25] @ W1[25x64] ----
        u64 acc[4][8];
        #pragma unroll
        for (int n = 0; n < 8; n++) {
            acc[0][n] = bp1[n]; acc[1][n] = bp1[n];
            acc[2][n] = bp1[n]; acc[3][n] = bp1[n];
        }
        #pragma unroll 5
        for (int k = 0; k < FEAT; k++) {
            const ulonglong2* ap = (const ulonglong2*)(buf + k*TILE_E + er*8);
            ulonglong2 aA = ap[0], aB = ap[1];
            const ulonglong2* wp = (const ulonglong2*)(sW1d + k*128 + nc*16);
            ulonglong2 w0 = wp[0], w1 = wp[1], w2 = wp[2], w3 = wp[3];
            const u64 wv[8] = {w0.x, w0.y, w1.x, w1.y, w2.x, w2.y, w3.x, w3.y};
            #pragma unroll
            for (int n = 0; n < 8; n++) {
                fma2(acc[0][n], aA.x, wv[n]);
                fma2(acc[1][n], aA.y, wv[n]);
                fma2(acc[2][n], aB.x, wv[n]);
                fma2(acc[3][n], aB.y, wv[n]);
            }
        }
        __syncthreads();   // feat reads done before H overlays buf

        // ---- silu + store H[k][e] ----
        #pragma unroll
        for (int n = 0; n < 8; n++) {
            int rowk = nc*8 + n;
            ulonglong2 s0, s1;
            s0.x = silu2(acc[0][n]); s0.y = silu2(acc[1][n]);
            s1.x = silu2(acc[2][n]); s1.y = silu2(acc[3][n]);
            ulonglong2* dp = (ulonglong2*)(buf + rowk*TILE_E + er*8);
            dp[0] = s0; dp[1] = s1;
        }
        __syncthreads();

        // ---- phase 3: GEMM2  EW = H[256x64] @ W2[64x64] (stays in regs) ----
        #pragma unroll
        for (int n = 0; n < 8; n++) {
            acc[0][n] = bp2[n]; acc[1][n] = bp2[n];
            acc[2][n] = bp2[n]; acc[3][n] = bp2[n];
        }
        #pragma unroll 4
        for (int k = 0; k < DD; k++) {
            const ulonglong2* ap = (const ulonglong2*)(buf + k*TILE_E + er*8);
            ulonglong2 aA = ap[0], aB = ap[1];
            const ulonglong2* wp = (const ulonglong2*)(sW2d + k*128 + nc*16);
            ulonglong2 w0 = wp[0], w1 = wp[1], w2 = wp[2], w3 = wp[3];
            const u64 wv[8] = {w0.x, w0.y, w1.x, w1.y, w2.x, w2.y, w3.x, w3.y};
            #pragma unroll
            for (int n = 0; n < 8; n++) {
                fma2(acc[0][n], aA.x, wv[n]);
                fma2(acc[1][n], aA.y, wv[n]);
                fma2(acc[2][n], aB.x, wv[n]);
                fma2(acc[3][n], aB.y, wv[n]);
            }
        }

        // ---- prefetch next tile's indices + direction (hide pos gather) ----
        const int nxt = tile + gridDim.x;
        if (nxt < NTILE) {
            const int e2 = nxt * TILE_E + t;
            pr_r = row[e2]; pr_c = col[e2];
            float px = pos[3*pr_r]   - pos[3*pr_c];
            float py = pos[3*pr_r+1] - pos[3*pr_c+1];
            float pz = pos[3*pr_r+2] - pos[3*pr_c+2];
            float len = sqrtf(px*px + py*py + pz*pz + 1e-12f);
            float dx = px / len, dy = py / len, dz = pz / len;
            float n2 = sqrtf(dx*dx + dy*dy + dz*dz) + 1e-10f;
            pr_dx = dx / n2; pr_dy = dy / n2; pr_dz = dz / n2;
        }

        // ---- phase 4: scatter straight from registers ----
        #pragma unroll
        for (int i = 0; i < 4; i++) {
            float lo[8], hi[8];
            #pragma unroll
            for (int n = 0; n < 8; n++) upk2(acc[i][n], lo[n], hi[n]);
            const int e0 = er*8 + 2*i;
            const int r0 = sRow[e0],   c0 = sCol[e0];
            const int r1 = sRow[e0+1], c1 = sCol[e0+1];
            {
                const float4* xp = (const float4*)(g_xt + (size_t)r0 * DD + nc*8);
                float4 xa = xp[0], xb = xp[1];
                float* sc = g_s + (size_t)c0 * DD + nc*8;
                red_add_v4(sc,     lo[0]*xa.x, lo[1]*xa.y, lo[2]*xa.z, lo[3]*xa.w);
                red_add_v4(sc + 4, lo[4]*xb.x, lo[5]*xb.y, lo[6]*xb.z, lo[7]*xb.w);
            }
            {
                const float4* xp = (const float4*)(g_xt + (size_t)r1 * DD + nc*8);
                float4 xa = xp[0], xb = xp[1];
                float* sc = g_s + (size_t)c1 * DD + nc*8;
                red_add_v4(sc,     hi[0]*xa.x, hi[1]*xa.y, hi[2]*xa.z, hi[3]*xa.w);
                red_add_v4(sc + 4, hi[4]*xb.x, hi[5]*xb.y, hi[6]*xb.z, hi[7]*xb.w);
            }
        }
        __syncthreads();   // protect buf/sRow/sCol before next tile
    }
}

// ---------------- agg = s / max(cnt,1), in place ---------------------------
__global__ void agg_kernel() {
    int idx = blockIdx.x * 256 + threadIdx.x;
    if (idx >= NN * (DD / 4)) return;
    int node = idx >> 4;
    float inv = 1.0f / fmaxf(g_cnt[node], 1.0f);
    float4 v = ((float4*)g_s)[idx];
    v.x *= inv; v.y *= inv; v.z *= inv; v.w *= inv;
    ((float4*)g_s)[idx] = v;
}

// ---------------- batch-norm normalize -------------------------------------
__global__ void bn_kernel(float* __restrict__ outp,
                          const float* __restrict__ gamma,
                          const float* __restrict__ beta)
{
    int idx = blockIdx.x * 256 + threadIdx.x;
    if (idx >= NN * (DD / 4)) return;
    int jb = (idx & 15) * 4;
    float4 h = ((const float4*)g_h)[idx];
    float r[4] = {h.x, h.y, h.z, h.w};
    float rr[4];
    #pragma unroll
    for (int u = 0; u < 4; u++) {
        int j = jb + u;
        double mu  = g_sum[j]   * (1.0 / NN);
        double var = g_sumsq[j] * (1.0 / NN) - mu * mu;
        float  sc  = gamma[j] * rsqrtf(fmaxf((float)var, 0.f) + 1e-5f);
        rr[u] = (float)((double)r[u] - mu) * sc + beta[j];
    }
    ((float4*)outp)[idx] = make_float4(rr[0], rr[1], rr[2], rr[3]);
}

// ---------------- launch ----------------------------------------------------
#define EDGE_SMEM ((3200 + 8192 + 512 + 16384) * 4)   // 113152 bytes

extern "C" void kernel_launch(void* const* d_in, const int* in_sizes, int n_in,
                              void* d_out, int out_size)
{
    const float* x         = (const float*)d_in[0];
    const float* pos       = (const float*)d_in[1];
    const float* edge_attr = (const float*)d_in[2];
    const int*   row       = (const int*)  d_in[3];
    const int*   col       = (const int*)  d_in[4];
    const float* nW1 = (const float*)d_in[5];
    const float* nb1 = (const float*)d_in[6];
    const float* nW2 = (const float*)d_in[7];
    const float* nb2 = (const float*)d_in[8];
    const float* eW1 = (const float*)d_in[9];
    const float* eb1 = (const float*)d_in[10];
    const float* eW2 = (const float*)d_in[11];
    const float* eb2 = (const float*)d_in[12];
    const float* oW1 = (const float*)d_in[13];
    const float* ob1 = (const float*)d_in[14];
    const float* oW2 = (const float*)d_in[15];
    const float* ob2 = (const float*)d_in[16];
    const float* gam = (const float*)d_in[17];
    const float* bet = (const float*)d_in[18];
    float* outp = (float*)d_out;

    cudaFuncSetAttribute(edge_kernel,
                         cudaFuncAttributeMaxDynamicSharedMemorySize, EDGE_SMEM);

    zero_kernel<<<512, 256>>>();
    mlp_kernel<false><<<(NN + 127) / 128, 128>>>(x, nW1, nb1, nW2, nb2);
    edge_kernel<<<296, 256, EDGE_SMEM>>>(pos, edge_attr, row, col, eW1, eb1, eW2, eb2);
    agg_kernel<<<(NN * (DD / 4) + 255) / 256, 256>>>();
    mlp_kernel<true><<<(NN + 127) / 128, 128>>>(x, oW1, ob1, oW2, ob2);
    bn_kernel<<<(NN * (DD / 4) + 255) / 256, 256>>>(outp, gam, bet);
}

// round 9
// speedup vs baseline: 1.7534x; 1.7534x over previous
#include <cuda_runtime.h>
#include <cuda_bf16.h>
#include <math.h>
#include <stdint.h>

#define NN 100000
#define EE 1600000
#define DD 64
#define EDIM 16
#define SHC 9
#define FEAT 25
#define TE 128            // edges per tile
#define NT (EE / TE)      // 12500

typedef unsigned long long u64;

// ---------------- scratch (device globals) ----------------------------------
__device__ float  g_xt[(size_t)NN * DD];
__device__ float  g_s [(size_t)NN * DD];
__device__ float  g_cnt[NN];
__device__ float  g_h [(size_t)NN * DD];
__device__ double g_sum[DD];
__device__ double g_sumsq[DD];

__device__ __forceinline__ float silu_f(float a) {
    return a / (1.0f + __expf(-a));
}
__device__ __forceinline__ u64 pk2(float x, float y) {
    u64 r; asm("mov.b64 %0, {%1,%2};" : "=l"(r) : "f"(x), "f"(y)); return r;
}
__device__ __forceinline__ void upk2(u64 v, float& x, float& y) {
    asm("mov.b64 {%0,%1}, %2;" : "=f"(x), "=f"(y) : "l"(v));
}
__device__ __forceinline__ void fma2(u64& d, u64 a, u64 b) {
    asm("fma.rn.f32x2 %0, %1, %2, %0;" : "+l"(d) : "l"(a), "l"(b));
}
__device__ __forceinline__ void red_add_v4(float* p, float a, float b, float c, float d) {
    asm volatile("red.global.add.v4.f32 [%0], {%1,%2,%3,%4};"
                 :: "l"(p), "f"(a), "f"(b), "f"(c), "f"(d) : "memory");
}
__device__ __forceinline__ uint32_t s2u(const void* p) {
    uint32_t a;
    asm("{ .reg .u64 t; cvta.to.shared.u64 t, %1; cvt.u32.u64 %0, t; }" : "=r"(a) : "l"(p));
    return a;
}

// ---------------- mma.sync / ldmatrix primitives (sm_80+, valid on sm_100) ---
__device__ __forceinline__ void ldsm4(uint32_t* r, uint32_t a) {
    asm volatile("ldmatrix.sync.aligned.m8n8.x4.shared.b16 {%0,%1,%2,%3}, [%4];"
                 : "=r"(r[0]), "=r"(r[1]), "=r"(r[2]), "=r"(r[3]) : "r"(a));
}
__device__ __forceinline__ void ldsm4t(uint32_t* r, uint32_t a) {
    asm volatile("ldmatrix.sync.aligned.m8n8.x4.trans.shared.b16 {%0,%1,%2,%3}, [%4];"
                 : "=r"(r[0]), "=r"(r[1]), "=r"(r[2]), "=r"(r[3]) : "r"(a));
}
__device__ __forceinline__ void mma16816(float* c, const uint32_t* a,
                                         uint32_t b0, uint32_t b1) {
    asm volatile(
        "mma.sync.aligned.m16n8k16.row.col.f32.bf16.bf16.f32 "
        "{%0,%1,%2,%3}, {%4,%5,%6,%7}, {%8,%9}, {%0,%1,%2,%3};"
        : "+f"(c[0]), "+f"(c[1]), "+f"(c[2]), "+f"(c[3])
        : "r"(a[0]), "r"(a[1]), "r"(a[2]), "r"(a[3]), "r"(b0), "r"(b1));
}

__device__ __forceinline__ void split8(const float* v, uint4& hi, uint4& lo) {
    uint32_t h[4], l[4];
    #pragma unroll
    for (int p = 0; p < 4; p++) {
        float a = v[2*p], b = v[2*p+1];
        __nv_bfloat162 hh = __floats2bfloat162_rn(a, b);
        float la = a - __bfloat162float(__low2bfloat16(hh));
        float lb = b - __bfloat162float(__high2bfloat16(hh));
        __nv_bfloat162 ll = __floats2bfloat162_rn(la, lb);
        h[p] = *(uint32_t*)&hh; l[p] = *(uint32_t*)&ll;
    }
    hi = make_uint4(h[0], h[1], h[2], h[3]);
    lo = make_uint4(l[0], l[1], l[2], l[3]);
}
__device__ __forceinline__ void split2(float a, float b, uint32_t& hi, uint32_t& lo) {
    __nv_bfloat162 hh = __floats2bfloat162_rn(a, b);
    float la = a - __bfloat162float(__low2bfloat16(hh));
    float lb = b - __bfloat162float(__high2bfloat16(hh));
    __nv_bfloat162 ll = __floats2bfloat162_rn(la, lb);
    hi = *(uint32_t*)&hh; lo = *(uint32_t*)&ll;
}

// ---------------- zero scratch ----------------------------------------------
__global__ void zero_kernel() {
    int idx = blockIdx.x * blockDim.x + threadIdx.x;
    int stride = gridDim.x * blockDim.x;
    float4 z = make_float4(0.f, 0.f, 0.f, 0.f);
    for (int i = idx; i < NN * (DD / 4); i += stride)
        ((float4*)g_s)[i] = z;
    for (int i = idx; i < NN; i += stride)
        g_cnt[i] = 0.f;
    if (idx < DD) { g_sum[idx] = 0.0; g_sumsq[idx] = 0.0; }
}

// ---------------- node / output MLP (R5, unchanged) --------------------------
template <bool IS_OUT>
__global__ __launch_bounds__(128)
void mlp_kernel(const float* __restrict__ x,
                const float* __restrict__ W1, const float* __restrict__ b1,
                const float* __restrict__ W2, const float* __restrict__ b2)
{
    constexpr int IND = IS_OUT ? 128 : 64;
    __shared__ __align__(16) float sW1[IND * DD];
    __shared__ __align__(16) float sW2[DD * DD];
    const int t = threadIdx.x;
    for (int i = t; i < IND * DD; i += 128) sW1[i] = W1[i];
    for (int i = t; i < DD * DD;  i += 128) sW2[i] = W2[i];
    __syncthreads();

    const int id = blockIdx.x * 128 + t;
    const bool valid = (id < NN);
    const int rid = valid ? id : (NN - 1);

    const float4* rowA;
    const float4* rowB = nullptr;
    if (IS_OUT) {
        rowA = (const float4*)(g_s + (size_t)rid * DD);
        rowB = (const float4*)(x   + (size_t)rid * DD);
    } else {
        rowA = (const float4*)(x + (size_t)rid * DD);
    }

    u64 outp[32];
    {
        const ulonglong2* b2v = (const ulonglong2*)b2;
        #pragma unroll
        for (int q = 0; q < 16; q++) { ulonglong2 bv = b2v[q]; outp[2*q] = bv.x; outp[2*q+1] = bv.y; }
    }

    #pragma unroll 1
    for (int ch = 0; ch < 4; ch++) {
        const int base = ch * 16;
        u64 hp[8];
        {
            const ulonglong2* b1v = (const ulonglong2*)(b1 + base);
            #pragma unroll
            for (int q = 0; q < 4; q++) { ulonglong2 bv = b1v[q]; hp[2*q] = bv.x; hp[2*q+1] = bv.y; }
        }
        #pragma unroll 2
        for (int g = 0; g < IND / 4; g++) {
            float4 v;
            if (IS_OUT) v = (g < 16) ? rowA[g] : rowB[g - 16];
            else        v = rowA[g];
            const float fv[4] = {v.x, v.y, v.z, v.w};
            #pragma unroll
            for (int u = 0; u < 4; u++) {
                const u64 fmp = pk2(fv[u], fv[u]);
                const ulonglong2* wr = (const ulonglong2*)(sW1 + (g*4 + u) * DD + base);
                #pragma unroll
                for (int q = 0; q < 4; q++) {
                    ulonglong2 w = wr[q];
                    fma2(hp[2*q], fmp, w.x);
                    fma2(hp[2*q+1], fmp, w.y);
                }
            }
        }
        float h16[16];
        #pragma unroll
        for (int i = 0; i < 8; i++) {
            float a, b; upk2(hp[i], a, b);
            h16[2*i] = silu_f(a); h16[2*i+1] = silu_f(b);
        }
        #pragma unroll
        for (int kk = 0; kk < 16; kk++) {
            const u64 hvp = pk2(h16[kk], h16[kk]);
            const ulonglong2* wr = (const ulonglong2*)(sW2 + (base + kk) * DD);
            #pragma unroll
            for (int q = 0; q < 16; q++) {
                ulonglong2 w = wr[q];
                fma2(outp[2*q], hvp, w.x);
                fma2(outp[2*q+1], hvp, w.y);
            }
        }
    }

    float* dst = IS_OUT ? g_h : g_xt;
    if (valid) {
        ulonglong2* o = (ulonglong2*)(dst + (size_t)id * DD);
        #pragma unroll
        for (int q = 0; q < 16; q++) {
            ulonglong2 w; w.x = outp[2*q]; w.y = outp[2*q+1];
            o[q] = w;
        }
    }

    if (IS_OUT) {
        #pragma unroll
        for (int jp = 0; jp < 32; jp++) {
            float va, vb; upk2(outp[jp], va, vb);
            if (!valid) { va = 0.f; vb = 0.f; }
            float s0 = va, q0 = va * va, s1 = vb, q1 = vb * vb;
            #pragma unroll
            for (int o = 16; o; o >>= 1) {
                s0 += __shfl_down_sync(0xffffffffu, s0, o);
                q0 += __shfl_down_sync(0xffffffffu, q0, o);
                s1 += __shfl_down_sync(0xffffffffu, s1, o);
                q1 += __shfl_down_sync(0xffffffffu, q1, o);
            }
            if ((t & 31) == 0) {
                atomicAdd(&g_sum[2*jp],     (double)s0);
                atomicAdd(&g_sumsq[2*jp],   (double)q0);
                atomicAdd(&g_sum[2*jp+1],   (double)s1);
                atomicAdd(&g_sumsq[2*jp+1], (double)q1);
            }
        }
    }
}

// ---------------- fused edge kernel: mma.sync bf16 hi/lo (3-pass) -----------
// Per 128-edge tile, 4 warps; warp w owns edges [w*32, w*32+32), all 64 outputs.
// GEMM1: D1 = feat[128xK32] @ W1[k][n]   (b1 folded as feature k=25, 3 passes)
// silu -> bf16 hi/lo -> A2;  GEMM2: D2 = A2[128xK64] @ W2[k][n] (3 passes)
// EW(f32, overlays A2) -> per-edge (D2+b2)*x_t[row] -> red.v4 scatter
#define SA1 80
#define SA2 144
#define SW  144
#define SEW 272
#define OFF_B2   0
#define OFF_A1H  256
#define OFF_A1L  10496
#define OFF_A2H  20736
#define OFF_A2L  39168
#define OFF_EW   20736       // overlays A2H..A2L (34816 <= 36864)
#define OFF_W1H  57600
#define OFF_W1L  62208
#define OFF_W2H  66816
#define OFF_W2L  76032
#define EDGE_SMEM 85248

__global__ __launch_bounds__(128, 2)
void edge_kernel(const float* __restrict__ pos,
                 const float* __restrict__ edge_attr,
                 const int*   __restrict__ row,
                 const int*   __restrict__ col,
                 const float* __restrict__ W1, const float* __restrict__ b1,
                 const float* __restrict__ W2, const float* __restrict__ b2)
{
    extern __shared__ __align__(16) char smem[];
    const uint32_t sb = s2u(smem);
    const int t    = threadIdx.x;
    const int wid  = t >> 5;
    const int lane = t & 31;
    const int m0   = wid * 32;

    float* sB2 = (float*)(smem + OFF_B2);

    // ---- one-time: weights -> bf16 hi/lo, [k][n] row-major, stride SW ----
    for (int i = t; i < 32 * 64; i += 128) {      // W1 (+bias row k=25, pad 26-31)
        int k = i >> 6, n = i & 63;
        float v = (k < FEAT) ? W1[k * 64 + n] : ((k == FEAT) ? b1[n] : 0.f);
        uint32_t o = (uint32_t)(k * SW + n * 2);
        __nv_bfloat16 h = __float2bfloat16(v);
        *(__nv_bfloat16*)(smem + OFF_W1H + o) = h;
        *(__nv_bfloat16*)(smem + OFF_W1L + o) = __float2bfloat16(v - __bfloat162float(h));
    }
    for (int i = t; i < 64 * 64; i += 128) {      // W2
        int k = i >> 6, n = i & 63;
        float v = W2[k * 64 + n];
        uint32_t o = (uint32_t)(k * SW + n * 2);
        __nv_bfloat16 h = __float2bfloat16(v);
        *(__nv_bfloat16*)(smem + OFF_W2H + o) = h;
        *(__nv_bfloat16*)(smem + OFF_W2L + o) = __float2bfloat16(v - __bfloat162float(h));
    }
    if (t < 64) sB2[t] = b2[t];
    __syncthreads();

    const uint32_t aA1H = sb + OFF_A1H, aA1L = sb + OFF_A1L;
    const uint32_t aA2H = sb + OFF_A2H, aA2L = sb + OFF_A2L;
    const uint32_t aW1H = sb + OFF_W1H, aW1L = sb + OFF_W1L;
    const uint32_t aW2H = sb + OFF_W2H, aW2L = sb + OFF_W2L;

    for (int tile = blockIdx.x; tile < NT; tile += gridDim.x) {
        const int e = tile * TE + t;
        const int r = row[e];
        const int c = col[e];

        // ---- phase 1: per-edge features (bf16 hi/lo) -> A1[t][0..31] ----
        {
            float px = pos[3*r]   - pos[3*c];
            float py = pos[3*r+1] - pos[3*c+1];
            float pz = pos[3*r+2] - pos[3*c+2];
            float len = sqrtf(px*px + py*py + pz*pz + 1e-12f);
            float dx = px / len, dy = py / len, dz = pz / len;
            float n2 = sqrtf(dx*dx + dy*dy + dz*dz) + 1e-10f;
            dx /= n2; dy /= n2; dz /= n2;

            float f[32];
            f[0] = 0.28209479177387814f;
            f[1] = 0.4886025119029199f * dy;
            f[2] = 0.4886025119029199f * dz;
            f[3] = 0.4886025119029199f * dx;
            f[4] = 1.0925484305920792f * dx * dy;
            f[5] = 1.0925484305920792f * dy * dz;
            f[6] = 0.31539156525252005f * (3.0f * dz * dz - 1.0f);
            f[7] = 1.0925484305920792f * dx * dz;
            f[8] = 0.5462742152960396f * (dx*dx - dy*dy);
            const float4* ea = (const float4*)(edge_attr + (size_t)e * EDIM);
            #pragma unroll
            for (int i = 0; i < 4; i++) {
                float4 v = ea[i];
                f[SHC + 4*i]   = v.x; f[SHC + 4*i+1] = v.y;
                f[SHC + 4*i+2] = v.z; f[SHC + 4*i+3] = v.w;
            }
            f[25] = 1.0f;                          // bias feature
            #pragma unroll
            for (int k = 26; k < 32; k++) f[k] = 0.f;

            #pragma unroll
            for (int cc = 0; cc < 4; cc++) {
                uint4 hi, lo;
                split8(f + cc*8, hi, lo);
                *(uint4*)(smem + OFF_A1H + t*SA1 + cc*16) = hi;
                *(uint4*)(smem + OFF_A1L + t*SA1 + cc*16) = lo;
            }
            atomicAdd(&g_cnt[c], 1.0f);
        }
        __syncthreads();

        // ---- GEMM1: C[2][8][4] over K=32, 3 passes ----
        float C[2][8][4];
        #pragma unroll
        for (int mf = 0; mf < 2; mf++)
            #pragma unroll
            for (int nf = 0; nf < 8; nf++)
                #pragma unroll
                for (int q = 0; q < 4; q++) C[mf][nf][q] = 0.f;

        #pragma unroll
        for (int pass = 0; pass < 3; pass++) {
            const uint32_t Ab = (pass == 2) ? aA1L : aA1H;
            const uint32_t Wb = (pass == 1) ? aW1L : aW1H;
            #pragma unroll
            for (int ks = 0; ks < 2; ks++) {
                uint32_t af[2][4];
                #pragma unroll
                for (int mf = 0; mf < 2; mf++)
                    ldsm4(af[mf], Ab + (uint32_t)((m0 + 16*mf + (lane & 15)) * SA1
                                                  + ks*32 + (lane >> 4) * 16));
                #pragma unroll
                for (int np = 0; np < 4; np++) {
                    uint32_t bf[4];
                    ldsm4t(bf, Wb + (uint32_t)((ks*16 + (lane & 7) + 8*((lane >> 3) & 1)) * SW
                                               + (np*16 + (lane >> 4) * 8) * 2));
                    #pragma unroll
                    for (int mf = 0; mf < 2; mf++) {
                        mma16816(C[mf][2*np],     af[mf], bf[0], bf[1]);
                        mma16816(C[mf][2*np + 1], af[mf], bf[2], bf[3]);
                    }
                }
            }
        }

        // ---- silu -> bf16 hi/lo -> A2 (rows = edges) ----
        #pragma unroll
        for (int mf = 0; mf < 2; mf++) {
            const int r0 = m0 + 16*mf + (lane >> 2);
            #pragma unroll
            for (int nf = 0; nf < 8; nf++) {
                const int cb = (nf*8 + 2*(lane & 3)) * 2;   // byte offset of col pair
                uint32_t hi, lo;
                split2(silu_f(C[mf][nf][0]), silu_f(C[mf][nf][1]), hi, lo);
                *(uint32_t*)(smem + OFF_A2H + r0*SA2 + cb) = hi;
                *(uint32_t*)(smem + OFF_A2L + r0*SA2 + cb) = lo;
                split2(silu_f(C[mf][nf][2]), silu_f(C[mf][nf][3]), hi, lo);
                *(uint32_t*)(smem + OFF_A2H + (r0+8)*SA2 + cb) = hi;
                *(uint32_t*)(smem + OFF_A2L + (r0+8)*SA2 + cb) = lo;
            }
        }
        __syncthreads();

        // ---- GEMM2: K=64, 3 passes ----
        #pragma unroll
        for (int mf = 0; mf < 2; mf++)
            #pragma unroll
            for (int nf = 0; nf < 8; nf++)
                #pragma unroll
                for (int q = 0; q < 4; q++) C[mf][nf][q] = 0.f;

        #pragma unroll
        for (int pass = 0; pass < 3; pass++) {
            const uint32_t Ab = (pass == 2) ? aA2L : aA2H;
            const uint32_t Wb = (pass == 1) ? aW2L : aW2H;
            #pragma unroll
            for (int ks = 0; ks < 4; ks++) {
                uint32_t af[2][4];
                #pragma unroll
                for (int mf = 0; mf < 2; mf++)
                    ldsm4(af[mf], Ab + (uint32_t)((m0 + 16*mf + (lane & 15)) * SA2
                                                  + ks*32 + (lane >> 4) * 16));
                #pragma unroll
                for (int np = 0; np < 4; np++) {
                    uint32_t bf[4];
                    ldsm4t(bf, Wb + (uint32_t)((ks*16 + (lane & 7) + 8*((lane >> 3) & 1)) * SW
                                               + (np*16 + (lane >> 4) * 8) * 2));
                    #pragma unroll
                    for (int mf = 0; mf < 2; mf++) {
                        mma16816(C[mf][2*np],     af[mf], bf[0], bf[1]);
                        mma16816(C[mf][2*np + 1], af[mf], bf[2], bf[3]);
                    }
                }
            }
        }
        __syncthreads();   // all A2 reads done before EW overlays it

        // ---- EW (f32) -> smem ----
        #pragma unroll
        for (int mf = 0; mf < 2; mf++) {
            const int r0 = m0 + 16*mf + (lane >> 2);
            #pragma unroll
            for (int nf = 0; nf < 8; nf++) {
                const int cb = (nf*8 + 2*(lane & 3)) * 4;   // byte offset (f32)
                *(float2*)(smem + OFF_EW + r0*SEW + cb)     = make_float2(C[mf][nf][0], C[mf][nf][1]);
                *(float2*)(smem + OFF_EW + (r0+8)*SEW + cb) = make_float2(C[mf][nf][2], C[mf][nf][3]);
            }
        }
        __syncthreads();

        // ---- scatter: msg = (EW[t] + b2) * x_t[r] -> s[c] ----
        {
            const float4* ew = (const float4*)(smem + OFF_EW + t*SEW);
            const float4* xp = (const float4*)(g_xt + (size_t)r * DD);
            const float4* bb = (const float4*)sB2;
            float* sc = g_s + (size_t)c * DD;
            #pragma unroll
            for (int q = 0; q < 16; q++) {
                float4 w = ew[q];
                float4 xv = xp[q];
                float4 bv = bb[q];
                red_add_v4(sc + 4*q,
                           (w.x + bv.x) * xv.x, (w.y + bv.y) * xv.y,
                           (w.z + bv.z) * xv.z, (w.w + bv.w) * xv.w);
            }
        }
        // no sync needed: next phase1 writes A1 (disjoint from EW); the
        // post-phase-1 barrier orders everything before EW is overwritten.
    }
}

// ---------------- agg = s / max(cnt,1), in place ---------------------------
__global__ void agg_kernel() {
    int idx = blockIdx.x * 256 + threadIdx.x;
    if (idx >= NN * (DD / 4)) return;
    int node = idx >> 4;
    float inv = 1.0f / fmaxf(g_cnt[node], 1.0f);
    float4 v = ((float4*)g_s)[idx];
    v.x *= inv; v.y *= inv; v.z *= inv; v.w *= inv;
    ((float4*)g_s)[idx] = v;
}

// ---------------- batch-norm normalize -------------------------------------
__global__ void bn_kernel(float* __restrict__ outp,
                          const float* __restrict__ gamma,
                          const float* __restrict__ beta)
{
    int idx = blockIdx.x * 256 + threadIdx.x;
    if (idx >= NN * (DD / 4)) return;
    int jb = (idx & 15) * 4;
    float4 h = ((const float4*)g_h)[idx];
    float r[4] = {h.x, h.y, h.z, h.w};
    float rr[4];
    #pragma unroll
    for (int u = 0; u < 4; u++) {
        int j = jb + u;
        double mu  = g_sum[j]   * (1.0 / NN);
        double var = g_sumsq[j] * (1.0 / NN) - mu * mu;
        float  sc  = gamma[j] * rsqrtf(fmaxf((float)var, 0.f) + 1e-5f);
        rr[u] = (float)((double)r[u] - mu) * sc + beta[j];
    }
    ((float4*)outp)[idx] = make_float4(rr[0], rr[1], rr[2], rr[3]);
}

// ---------------- launch ----------------------------------------------------
extern "C" void kernel_launch(void* const* d_in, const int* in_sizes, int n_in,
                              void* d_out, int out_size)
{
    const float* x         = (const float*)d_in[0];
    const float* pos       = (const float*)d_in[1];
    const float* edge_attr = (const float*)d_in[2];
    const int*   row       = (const int*)  d_in[3];
    const int*   col       = (const int*)  d_in[4];
    const float* nW1 = (const float*)d_in[5];
    const float* nb1 = (const float*)d_in[6];
    const float* nW2 = (const float*)d_in[7];
    const float* nb2 = (const float*)d_in[8];
    const float* eW1 = (const float*)d_in[9];
    const float* eb1 = (const float*)d_in[10];
    const float* eW2 = (const float*)d_in[11];
    const float* eb2 = (const float*)d_in[12];
    const float* oW1 = (const float*)d_in[13];
    const float* ob1 = (const float*)d_in[14];
    const float* oW2 = (const float*)d_in[15];
    const float* ob2 = (const float*)d_in[16];
    const float* gam = (const float*)d_in[17];
    const float* bet = (const float*)d_in[18];
    float* outp = (float*)d_out;

    cudaFuncSetAttribute(edge_kernel,
                         cudaFuncAttributeMaxDynamicSharedMemorySize, EDGE_SMEM);

    zero_kernel<<<512, 256>>>();
    mlp_kernel<false><<<(NN + 127) / 128, 128>>>(x, nW1, nb1, nW2, nb2);
    edge_kernel<<<296, 128, EDGE_SMEM>>>(pos, edge_attr, row, col, eW1, eb1, eW2, eb2);
    agg_kernel<<<(NN * (DD / 4) + 255) / 256, 256>>>();
    mlp_kernel<true><<<(NN + 127) / 128, 128>>>(x, oW1, ob1, oW2, ob2);
    bn_kernel<<<(NN * (DD / 4) + 255) / 256, 256>>>(outp, gam, bet);
}